// round 5
// baseline (speedup 1.0000x reference)
#include <cuda_runtime.h>
#include <math.h>
#include <stdint.h>

#define B_   4
#define S_   2048
#define D_   2048
#define H_   16
#define HD_  128
#define DFF_ 8192
#define M_   (B_*S_)

// ---------------- scratch (static device globals; no allocation) ----------------
__device__ float g_h  [(size_t)M_*D_];
__device__ float g_q  [(size_t)M_*D_];
__device__ float g_k  [(size_t)M_*D_];
__device__ float g_v  [(size_t)M_*D_];
__device__ float g_o  [(size_t)M_*D_];
__device__ float g_x1 [(size_t)M_*D_];
__device__ float g_mid[(size_t)M_*DFF_];
__device__ float g_wqT [(size_t)D_*D_];
__device__ float g_wkT [(size_t)D_*D_];
__device__ float g_wvT [(size_t)D_*D_];
__device__ float g_woT [(size_t)D_*D_];
__device__ float g_fc1T[(size_t)DFF_*D_];   // [DFF, D]
__device__ float g_fc2T[(size_t)D_*DFF_];   // [D, DFF]

__device__ __forceinline__ float gelu_new_f(float x) {
    const float c = 0.7978845608028654f;
    return 0.5f * x * (1.0f + tanhf(c * (x + 0.044715f * x * x * x)));
}

// round-to-nearest tf32 (zero-mean rounding -> incoherent error accumulation)
__device__ __forceinline__ float tf32r(float x) {
    uint32_t r;
    asm("cvt.rna.tf32.f32 %0, %1;" : "=r"(r) : "f"(x));
    return __uint_as_float(r);
}

__device__ __forceinline__ uint32_t smem_u32(const void* p) {
    uint32_t a;
    asm("{ .reg .u64 t; cvta.to.shared.u64 t, %1; cvt.u32.u64 %0, t; }" : "=r"(a) : "l"(p));
    return a;
}

__device__ __forceinline__ void mma_tf32(float* d,
                                         uint32_t a0, uint32_t a1, uint32_t a2, uint32_t a3,
                                         uint32_t b0, uint32_t b1) {
    asm volatile("mma.sync.aligned.m16n8k8.row.col.f32.tf32.tf32.f32 "
                 "{%0,%1,%2,%3}, {%4,%5,%6,%7}, {%8,%9}, {%0,%1,%2,%3};"
                 : "+f"(d[0]), "+f"(d[1]), "+f"(d[2]), "+f"(d[3])
                 : "r"(a0), "r"(a1), "r"(a2), "r"(a3), "r"(b0), "r"(b1));
}

#define CP_ASYNC16(dst_u32, src_ptr) \
    asm volatile("cp.async.cg.shared.global [%0], [%1], 16;" :: "r"(dst_u32), "l"(src_ptr))
#define CP_COMMIT() asm volatile("cp.async.commit_group;" ::: "memory")
#define CP_WAIT1()  asm volatile("cp.async.wait_group 1;" ::: "memory")
#define CP_WAIT0()  asm volatile("cp.async.wait_group 0;" ::: "memory")

// ---------------- LayerNorm (tf32-rounded output: feeds GEMMs only) ----------------
__global__ __launch_bounds__(256) void ln_kernel(const float* __restrict__ x,
                                                 const float* __restrict__ w,
                                                 const float* __restrict__ b,
                                                 float* __restrict__ out) {
    __shared__ float redA[8], redB[8];
    size_t row = blockIdx.x;
    const float* xr = x + row * D_;
    float* orow = out + row * D_;
    int t = threadIdx.x, lane = t & 31, wid = t >> 5;
    float v[8];
    float4 f0 = *(const float4*)(xr + t * 4);
    float4 f1 = *(const float4*)(xr + 1024 + t * 4);
    v[0]=f0.x; v[1]=f0.y; v[2]=f0.z; v[3]=f0.w;
    v[4]=f1.x; v[5]=f1.y; v[6]=f1.z; v[7]=f1.w;
    float s = 0.f;
    #pragma unroll
    for (int i = 0; i < 8; i++) s += v[i];
    #pragma unroll
    for (int o2 = 16; o2 > 0; o2 >>= 1) s += __shfl_xor_sync(0xffffffffu, s, o2);
    if (!lane) redA[wid] = s;
    __syncthreads();
    float tot = 0.f;
    #pragma unroll
    for (int i = 0; i < 8; i++) tot += redA[i];
    float mu = tot * (1.0f / (float)D_);
    float sq = 0.f;
    #pragma unroll
    for (int i = 0; i < 8; i++) { float d = v[i] - mu; sq += d * d; }
    #pragma unroll
    for (int o2 = 16; o2 > 0; o2 >>= 1) sq += __shfl_xor_sync(0xffffffffu, sq, o2);
    if (!lane) redB[wid] = sq;
    __syncthreads();
    float var = 0.f;
    #pragma unroll
    for (int i = 0; i < 8; i++) var += redB[i];
    var *= (1.0f / (float)D_);
    float inv = rsqrtf(var + 1e-5f);
    float4 w0 = *(const float4*)(w + t * 4);
    float4 w1 = *(const float4*)(w + 1024 + t * 4);
    float4 b0 = *(const float4*)(b + t * 4);
    float4 b1 = *(const float4*)(b + 1024 + t * 4);
    float4 r0, r1;
    r0.x = tf32r((v[0]-mu)*inv*w0.x + b0.x);  r0.y = tf32r((v[1]-mu)*inv*w0.y + b0.y);
    r0.z = tf32r((v[2]-mu)*inv*w0.z + b0.z);  r0.w = tf32r((v[3]-mu)*inv*w0.w + b0.w);
    r1.x = tf32r((v[4]-mu)*inv*w1.x + b1.x);  r1.y = tf32r((v[5]-mu)*inv*w1.y + b1.y);
    r1.z = tf32r((v[6]-mu)*inv*w1.z + b1.z);  r1.w = tf32r((v[7]-mu)*inv*w1.w + b1.w);
    *(float4*)(orow + t * 4) = r0;
    *(float4*)(orow + 1024 + t * 4) = r1;
}

// ---------------- transpose [R,C] -> [C,R], tf32-rounded ----------------
__global__ __launch_bounds__(256) void transpose_k(const float* __restrict__ in,
                                                   float* __restrict__ out, int R, int C) {
    __shared__ float t[32][33];
    int bx = blockIdx.x * 32, by = blockIdx.y * 32;
    int x = bx + threadIdx.x;
    #pragma unroll
    for (int i = 0; i < 32; i += 8)
        t[threadIdx.y + i][threadIdx.x] = in[(size_t)(by + threadIdx.y + i) * C + x];
    __syncthreads();
    int x2 = by + threadIdx.x;
    #pragma unroll
    for (int i = 0; i < 32; i += 8)
        out[(size_t)(bx + threadIdx.y + i) * R + x2] = tf32r(t[threadIdx.x][threadIdx.y + i]);
}

// ---------------- fused flash attention ----------------
// grid (S/64, B*H), 128 threads (4 warps). CTA: 64 q rows of one (b,h).
// q,k,v,o in [b, s, h*hd] layout (tf32-rounded by producers).
#define FSTR 132
__global__ __launch_bounds__(128, 2) void flash_kernel(
    const float* __restrict__ q, const float* __restrict__ k,
    const float* __restrict__ v, float* __restrict__ o)
{
    extern __shared__ float fsm[];
    float* Ks = fsm;
    float* Vs = fsm + 64 * FSTR;

    int bh = blockIdx.y;
    int bb = bh >> 4, hh = bh & 15;
    size_t base = ((size_t)bb * S_) * D_ + (size_t)hh * HD_;
    int q0 = blockIdx.x * 64;

    int tid = threadIdx.x;
    int wid = tid >> 5, lane = tid & 31;
    int g = lane >> 2, tig = lane & 3;
    const uint32_t FULL = 0xffffffffu;

    // ---- stage Q tile through Ks (coalesced), read fragments to registers ----
    #pragma unroll
    for (int i = 0; i < 16; i++) {
        int idx = i * 128 + tid;
        int row = idx >> 5, c4 = idx & 31;
        float4 vv = *(const float4*)(q + base + (size_t)(q0 + row) * D_ + c4 * 4);
        *(float4*)(Ks + row * FSTR + c4 * 4) = vv;
    }
    __syncthreads();
    uint32_t qa[16][4];
    {
        int r0 = wid * 16 + g;
        #pragma unroll
        for (int kk = 0; kk < 16; kk++) {
            qa[kk][0] = __float_as_uint(Ks[r0 * FSTR + kk * 8 + tig]);
            qa[kk][1] = __float_as_uint(Ks[(r0 + 8) * FSTR + kk * 8 + tig]);
            qa[kk][2] = __float_as_uint(Ks[r0 * FSTR + kk * 8 + tig + 4]);
            qa[kk][3] = __float_as_uint(Ks[(r0 + 8) * FSTR + kk * 8 + tig + 4]);
        }
    }

    float oacc[16][4];
    #pragma unroll
    for (int i = 0; i < 16; i++) { oacc[i][0]=0.f; oacc[i][1]=0.f; oacc[i][2]=0.f; oacc[i][3]=0.f; }
    float mr0 = -1e30f, mr1 = -1e30f, l0 = 0.f, l1 = 0.f;

    for (int chunk = 0; chunk < S_ / 64; chunk++) {
        int kv0 = chunk * 64;
        __syncthreads();   // everyone done with prev Ks/Vs (and Q staging on iter 0)
        #pragma unroll
        for (int i = 0; i < 16; i++) {
            int idx = i * 128 + tid;
            int row = idx >> 5, c4 = idx & 31;
            CP_ASYNC16(smem_u32(Ks + row * FSTR + c4 * 4),
                       k + base + (size_t)(kv0 + row) * D_ + c4 * 4);
        }
        CP_COMMIT();
        #pragma unroll
        for (int i = 0; i < 16; i++) {
            int idx = i * 128 + tid;
            int row = idx >> 5, c4 = idx & 31;
            CP_ASYNC16(smem_u32(Vs + row * FSTR + c4 * 4),
                       v + base + (size_t)(kv0 + row) * D_ + c4 * 4);
        }
        CP_COMMIT();
        CP_WAIT1();        // K ready; V still in flight
        __syncthreads();

        // ---- S = Q K^T (warp: 16q x 64kv) ----
        float sacc[8][4];
        #pragma unroll
        for (int nt = 0; nt < 8; nt++) { sacc[nt][0]=0.f; sacc[nt][1]=0.f; sacc[nt][2]=0.f; sacc[nt][3]=0.f; }
        #pragma unroll
        for (int kk = 0; kk < 16; kk++) {
            #pragma unroll
            for (int nt = 0; nt < 8; nt++) {
                uint32_t b0 = __float_as_uint(Ks[(nt * 8 + g) * FSTR + kk * 8 + tig]);
                uint32_t b1 = __float_as_uint(Ks[(nt * 8 + g) * FSTR + kk * 8 + tig + 4]);
                mma_tf32(sacc[nt], qa[kk][0], qa[kk][1], qa[kk][2], qa[kk][3], b0, b1);
            }
        }
        const float scl = 0.08838834764831845f;
        #pragma unroll
        for (int nt = 0; nt < 8; nt++) {
            sacc[nt][0] *= scl; sacc[nt][1] *= scl; sacc[nt][2] *= scl; sacc[nt][3] *= scl;
        }

        // ---- online softmax ----
        float mx0 = -1e30f, mx1 = -1e30f;
        #pragma unroll
        for (int nt = 0; nt < 8; nt++) {
            mx0 = fmaxf(mx0, fmaxf(sacc[nt][0], sacc[nt][1]));
            mx1 = fmaxf(mx1, fmaxf(sacc[nt][2], sacc[nt][3]));
        }
        mx0 = fmaxf(mx0, __shfl_xor_sync(FULL, mx0, 1));
        mx0 = fmaxf(mx0, __shfl_xor_sync(FULL, mx0, 2));
        mx1 = fmaxf(mx1, __shfl_xor_sync(FULL, mx1, 1));
        mx1 = fmaxf(mx1, __shfl_xor_sync(FULL, mx1, 2));
        float mn0 = fmaxf(mr0, mx0), mn1 = fmaxf(mr1, mx1);
        float cr0 = __expf(mr0 - mn0), cr1 = __expf(mr1 - mn1);
        mr0 = mn0; mr1 = mn1;
        float rs0 = 0.f, rs1 = 0.f;
        #pragma unroll
        for (int nt = 0; nt < 8; nt++) {
            sacc[nt][0] = __expf(sacc[nt][0] - mn0); rs0 += sacc[nt][0];
            sacc[nt][1] = __expf(sacc[nt][1] - mn0); rs0 += sacc[nt][1];
            sacc[nt][2] = __expf(sacc[nt][2] - mn1); rs1 += sacc[nt][2];
            sacc[nt][3] = __expf(sacc[nt][3] - mn1); rs1 += sacc[nt][3];
        }
        rs0 += __shfl_xor_sync(FULL, rs0, 1);  rs0 += __shfl_xor_sync(FULL, rs0, 2);
        rs1 += __shfl_xor_sync(FULL, rs1, 1);  rs1 += __shfl_xor_sync(FULL, rs1, 2);
        l0 = l0 * cr0 + rs0;  l1 = l1 * cr1 + rs1;
        #pragma unroll
        for (int nt = 0; nt < 16; nt++) {
            oacc[nt][0] *= cr0; oacc[nt][1] *= cr0; oacc[nt][2] *= cr1; oacc[nt][3] *= cr1;
        }
        #pragma unroll
        for (int nt = 0; nt < 8; nt++) {
            sacc[nt][0] = tf32r(sacc[nt][0]); sacc[nt][1] = tf32r(sacc[nt][1]);
            sacc[nt][2] = tf32r(sacc[nt][2]); sacc[nt][3] = tf32r(sacc[nt][3]);
        }

        CP_WAIT0();        // V ready
        __syncthreads();

        // ---- O += P V ----
        int src  = g * 4 + (tig >> 1);
        int src2 = src + 2;
        int odd  = tig & 1;
        #pragma unroll
        for (int j = 0; j < 8; j++) {
            float e, od;
            e  = __shfl_sync(FULL, sacc[j][0], src);
            od = __shfl_sync(FULL, sacc[j][1], src);
            uint32_t a0 = __float_as_uint(odd ? od : e);
            e  = __shfl_sync(FULL, sacc[j][2], src);
            od = __shfl_sync(FULL, sacc[j][3], src);
            uint32_t a1 = __float_as_uint(odd ? od : e);
            e  = __shfl_sync(FULL, sacc[j][0], src2);
            od = __shfl_sync(FULL, sacc[j][1], src2);
            uint32_t a2 = __float_as_uint(odd ? od : e);
            e  = __shfl_sync(FULL, sacc[j][2], src2);
            od = __shfl_sync(FULL, sacc[j][3], src2);
            uint32_t a3 = __float_as_uint(odd ? od : e);
            #pragma unroll
            for (int nt = 0; nt < 16; nt++) {
                uint32_t b0 = __float_as_uint(Vs[(j * 8 + tig) * FSTR + nt * 8 + g]);
                uint32_t b1 = __float_as_uint(Vs[(j * 8 + tig + 4) * FSTR + nt * 8 + g]);
                mma_tf32(oacc[nt], a0, a1, a2, a3, b0, b1);
            }
        }
    }

    // ---- epilogue: normalize, tf32-round (feeds Wo GEMM), store ----
    float inv0 = 1.f / l0, inv1 = 1.f / l1;
    int r0 = q0 + wid * 16 + g;
    #pragma unroll
    for (int nt = 0; nt < 16; nt++) {
        int col = nt * 8 + 2 * tig;
        float2 s0, s1;
        s0.x = tf32r(oacc[nt][0] * inv0); s0.y = tf32r(oacc[nt][1] * inv0);
        s1.x = tf32r(oacc[nt][2] * inv1); s1.y = tf32r(oacc[nt][3] * inv1);
        *(float2*)(o + base + (size_t)r0 * D_ + col)       = s0;
        *(float2*)(o + base + (size_t)(r0 + 8) * D_ + col) = s1;
    }
}

// ---------------- tf32 mma.sync GEMM: C[M,N] = epi(alpha * A[M,K] @ B[N,K]^T) --------
// EPI: 0=alpha*acc ; 1=gelu(acc+bias) ; 2=acc+resid ; 3=acc+bias+resid
#define ASTR 36
template<int EPI, bool TR>
__global__ __launch_bounds__(256, 2) void tgemm(
    const float* __restrict__ A, int lda,
    const float* __restrict__ Bm, int ldb,
    float* __restrict__ C, int ldc,
    int K, float alpha,
    const float* __restrict__ bias,
    const float* __restrict__ resid)
{
    extern __shared__ float sm[];
    float* Abuf[2] = { sm,        sm + 9216  };
    float* Bbuf[2] = { sm + 4608, sm + 13824 };

    int m0 = blockIdx.y * 128;
    int n0 = blockIdx.x * 128;
    int tid = threadIdx.x;
    int wid = tid >> 5, lane = tid & 31;
    int g = lane >> 2, tig = lane & 3;
    int warpM = wid >> 2, warpN = wid & 3;

    const float* Abase = A  + (size_t)m0 * lda;
    const float* Bbase = Bm + (size_t)n0 * ldb;

    float acc[4][4][4];
    #pragma unroll
    for (int i = 0; i < 4; i++)
        #pragma unroll
        for (int j = 0; j < 4; j++)
            #pragma unroll
            for (int r = 0; r < 4; r++) acc[i][j][r] = 0.f;

    int KT = K >> 5;

#define ISSUE_TILE(kt, bsel) do {                                              \
    const float* Ag_ = Abase + (kt) * 32;                                      \
    const float* Bg_ = Bbase + (kt) * 32;                                      \
    _Pragma("unroll")                                                          \
    for (int i_ = 0; i_ < 4; i_++) {                                           \
        int idx_ = i_ * 256 + tid;                                             \
        int row_ = idx_ >> 3, c4_ = idx_ & 7;                                  \
        uint32_t da_ = smem_u32(Abuf[bsel] + row_ * ASTR + c4_ * 4);           \
        CP_ASYNC16(da_, Ag_ + (size_t)row_ * lda + c4_ * 4);                   \
    }                                                                          \
    _Pragma("unroll")                                                          \
    for (int i_ = 0; i_ < 4; i_++) {                                           \
        int idx_ = i_ * 256 + tid;                                             \
        int row_ = idx_ >> 3, c4_ = idx_ & 7;                                  \
        uint32_t db_ = smem_u32(Bbuf[bsel] + row_ * ASTR + c4_ * 4);           \
        CP_ASYNC16(db_, Bg_ + (size_t)row_ * ldb + c4_ * 4);                   \
    }                                                                          \
    CP_COMMIT();                                                               \
} while (0)

    ISSUE_TILE(0, 0);

    for (int kt = 0; kt < KT; kt++) {
        int bsel = kt & 1;
        if (kt + 1 < KT) { ISSUE_TILE(kt + 1, bsel ^ 1); CP_WAIT1(); }
        else             { CP_WAIT0(); }
        __syncthreads();

        const uint32_t* As = (const uint32_t*)Abuf[bsel];
        const uint32_t* Bs = (const uint32_t*)Bbuf[bsel];
        #pragma unroll
        for (int kk = 0; kk < 4; kk++) {
            uint32_t af[4][4];
            #pragma unroll
            for (int mt = 0; mt < 4; mt++) {
                const uint32_t* p = As + (warpM * 64 + mt * 16 + g) * ASTR + kk * 8 + tig;
                af[mt][0] = p[0];
                af[mt][1] = p[8 * ASTR];
                af[mt][2] = p[4];
                af[mt][3] = p[8 * ASTR + 4];
            }
            uint32_t bf[4][2];
            #pragma unroll
            for (int nt = 0; nt < 4; nt++) {
                const uint32_t* p = Bs + (warpN * 32 + nt * 8 + g) * ASTR + kk * 8 + tig;
                bf[nt][0] = p[0];
                bf[nt][1] = p[4];
            }
            #pragma unroll
            for (int mt = 0; mt < 4; mt++)
                #pragma unroll
                for (int nt = 0; nt < 4; nt++)
                    mma_tf32(acc[mt][nt], af[mt][0], af[mt][1], af[mt][2], af[mt][3],
                             bf[nt][0], bf[nt][1]);
        }
        __syncthreads();
    }
#undef ISSUE_TILE

    #pragma unroll
    for (int mt = 0; mt < 4; mt++) {
        #pragma unroll
        for (int nt = 0; nt < 4; nt++) {
            int r0 = m0 + warpM * 64 + mt * 16 + g;
            int cN = n0 + warpN * 32 + nt * 8 + 2 * tig;
            #pragma unroll
            for (int hh = 0; hh < 2; hh++) {
                int rr = r0 + hh * 8;
                float e0 = acc[mt][nt][2 * hh + 0];
                float e1 = acc[mt][nt][2 * hh + 1];
                if (EPI == 0) { e0 *= alpha; e1 *= alpha; }
                if (EPI == 1 || EPI == 3) {
                    float2 bb = *(const float2*)(bias + cN);
                    e0 += bb.x; e1 += bb.y;
                }
                if (EPI == 1) { e0 = gelu_new_f(e0); e1 = gelu_new_f(e1); }
                if (EPI == 2 || EPI == 3) {
                    float2 rv = *(const float2*)(resid + (size_t)rr * ldc + cN);
                    e0 += rv.x; e1 += rv.y;
                }
                if (TR) { e0 = tf32r(e0); e1 = tf32r(e1); }
                float2 st; st.x = e0; st.y = e1;
                *(float2*)(C + (size_t)rr * ldc + cN) = st;
            }
        }
    }
}

// ---------------- host ----------------
static const int DSM  = 2 * 2 * 4608 * 4;       // 73728 bytes (tgemm)
static const int FDSM = 2 * 64 * FSTR * 4;      // 67584 bytes (flash)

extern "C" void kernel_launch(void* const* d_in, const int* in_sizes, int n_in,
                              void* d_out, int out_size) {
    (void)in_sizes; (void)n_in; (void)out_size;
    const float* x    = (const float*)d_in[0];
    const float* wq   = (const float*)d_in[1];
    const float* wk   = (const float*)d_in[2];
    const float* wv   = (const float*)d_in[3];
    const float* wo   = (const float*)d_in[4];
    const float* ln1w = (const float*)d_in[5];
    const float* ln1b = (const float*)d_in[6];
    const float* ln2w = (const float*)d_in[7];
    const float* ln2b = (const float*)d_in[8];
    const float* fc1w = (const float*)d_in[9];
    const float* fc1b = (const float*)d_in[10];
    const float* fc2w = (const float*)d_in[11];
    const float* fc2b = (const float*)d_in[12];
    float* out = (float*)d_out;

    float *h, *q, *k, *v, *o, *x1, *mid;
    float *wqT, *wkT, *wvT, *woT, *fc1T, *fc2T;
    cudaGetSymbolAddress((void**)&h,    g_h);
    cudaGetSymbolAddress((void**)&q,    g_q);
    cudaGetSymbolAddress((void**)&k,    g_k);
    cudaGetSymbolAddress((void**)&v,    g_v);
    cudaGetSymbolAddress((void**)&o,    g_o);
    cudaGetSymbolAddress((void**)&x1,   g_x1);
    cudaGetSymbolAddress((void**)&mid,  g_mid);
    cudaGetSymbolAddress((void**)&wqT,  g_wqT);
    cudaGetSymbolAddress((void**)&wkT,  g_wkT);
    cudaGetSymbolAddress((void**)&wvT,  g_wvT);
    cudaGetSymbolAddress((void**)&woT,  g_woT);
    cudaGetSymbolAddress((void**)&fc1T, g_fc1T);
    cudaGetSymbolAddress((void**)&fc2T, g_fc2T);

    cudaFuncSetAttribute(tgemm<0,true >, cudaFuncAttributeMaxDynamicSharedMemorySize, DSM);
    cudaFuncSetAttribute(tgemm<0,false>, cudaFuncAttributeMaxDynamicSharedMemorySize, DSM);
    cudaFuncSetAttribute(tgemm<2,false>, cudaFuncAttributeMaxDynamicSharedMemorySize, DSM);
    cudaFuncSetAttribute(tgemm<1,true >, cudaFuncAttributeMaxDynamicSharedMemorySize, DSM);
    cudaFuncSetAttribute(tgemm<3,false>, cudaFuncAttributeMaxDynamicSharedMemorySize, DSM);
    cudaFuncSetAttribute(flash_kernel,   cudaFuncAttributeMaxDynamicSharedMemorySize, FDSM);

    dim3 blk(256);
    dim3 tb(32, 8);

    // --- weight transposes (graph-resident, tf32-rounded) ---
    transpose_k<<<dim3(D_/32,   D_/32),  tb>>>(wq,   wqT,  D_,   D_);
    transpose_k<<<dim3(D_/32,   D_/32),  tb>>>(wk,   wkT,  D_,   D_);
    transpose_k<<<dim3(D_/32,   D_/32),  tb>>>(wv,   wvT,  D_,   D_);
    transpose_k<<<dim3(D_/32,   D_/32),  tb>>>(wo,   woT,  D_,   D_);
    transpose_k<<<dim3(DFF_/32, D_/32),  tb>>>(fc1w, fc1T, D_,   DFF_);
    transpose_k<<<dim3(D_/32,   DFF_/32),tb>>>(fc2w, fc2T, DFF_, D_);

    // --- LN1 ---
    ln_kernel<<<M_, 256>>>(x, ln1w, ln1b, h);

    // --- Q, K, V projections (tf32-rounded outputs) ---
    dim3 g1(D_ / 128, M_ / 128, 1);
    tgemm<0,true ><<<g1, blk, DSM>>>(h, D_, wqT, D_, q, D_, D_, 1.f, 0, 0);
    tgemm<0,true ><<<g1, blk, DSM>>>(h, D_, wkT, D_, k, D_, D_, 1.f, 0, 0);
    tgemm<0,true ><<<g1, blk, DSM>>>(h, D_, wvT, D_, v, D_, D_, 1.f, 0, 0);

    // --- fused flash attention ---
    flash_kernel<<<dim3(S_/64, B_*H_), 128, FDSM>>>(q, k, v, o);

    // --- out-projection + residual (full fp32 residual stream) ---
    tgemm<2,false><<<g1, blk, DSM>>>(o, D_, woT, D_, x1, D_, D_, 1.f, 0, x);

    // --- LN2 ---
    ln_kernel<<<M_, 256>>>(x1, ln2w, ln2b, h);

    // --- FC1 + bias + gelu (tf32-rounded) ---
    dim3 g4(DFF_ / 128, M_ / 128, 1);
    tgemm<1,true ><<<g4, blk, DSM>>>(h, D_, fc1T, D_, mid, DFF_, D_, 1.f, fc1b, 0);

    // --- FC2 + bias + residual -> out (full fp32) ---
    tgemm<3,false><<<g1, blk, DSM>>>(mid, DFF_, fc2T, DFF_, out, D_, DFF_, 1.f, fc2b, x1);
}